// round 1
// baseline (speedup 1.0000x reference)
#include <cuda_runtime.h>
#include <cstdint>

#define Bc 2
#define Sc 2048
#define Dc 1024
#define Hc 16
#define HDc 64
#define SCALEc 0.125f   // 64^-0.5

// scratch (allocation-free rule: __device__ globals)
__device__ float g_Q[(size_t)Bc * Sc * Dc];
__device__ float g_K[(size_t)Bc * Sc * Dc];
__device__ float g_V[(size_t)Bc * Sc * Dc];
__device__ float g_ctx[(size_t)Bc * Sc * Dc];
// fallback attn buffer in case d_out only holds `output`
__device__ float g_attn_fb[(size_t)Bc * Hc * Sc * Sc];

// ---------------------------------------------------------------------------
// Generic tiled GEMM with bias: C[M,N] = A[M,K] @ W[K,N] + b[N]
// BM=BN=64, BK=16, 256 threads, 4x4 microtile per thread.
// ---------------------------------------------------------------------------
__global__ void gemm_bias_kernel(const float* __restrict__ A,
                                 const float* __restrict__ W,
                                 const float* __restrict__ bias,
                                 float* __restrict__ C,
                                 int M, int N, int K) {
    __shared__ float As[16][64];
    __shared__ float Bs[16][64];
    const int tx = threadIdx.x & 15;
    const int ty = threadIdx.x >> 4;
    const int row0 = blockIdx.y * 64;
    const int col0 = blockIdx.x * 64;

    float acc[4][4] = {};

    for (int k0 = 0; k0 < K; k0 += 16) {
        // A tile: 64 rows x 16 cols
        for (int i = threadIdx.x; i < 64 * 16; i += 256) {
            int r = i >> 4, c = i & 15;
            As[c][r] = A[(size_t)(row0 + r) * K + k0 + c];
        }
        // W tile: 16 rows x 64 cols
        for (int i = threadIdx.x; i < 16 * 64; i += 256) {
            int r = i >> 6, c = i & 63;
            Bs[r][c] = W[(size_t)(k0 + r) * N + col0 + c];
        }
        __syncthreads();
#pragma unroll
        for (int kk = 0; kk < 16; kk++) {
            float a[4], bb[4];
#pragma unroll
            for (int i = 0; i < 4; i++) a[i] = As[kk][ty * 4 + i];
#pragma unroll
            for (int j = 0; j < 4; j++) bb[j] = Bs[kk][tx * 4 + j];
#pragma unroll
            for (int i = 0; i < 4; i++)
#pragma unroll
                for (int j = 0; j < 4; j++) acc[i][j] += a[i] * bb[j];
        }
        __syncthreads();
    }

#pragma unroll
    for (int i = 0; i < 4; i++)
#pragma unroll
        for (int j = 0; j < 4; j++)
            C[(size_t)(row0 + ty * 4 + i) * N + col0 + tx * 4 + j] =
                acc[i][j] + bias[col0 + tx * 4 + j];
}

// ---------------------------------------------------------------------------
// scores[b,h,q,k] = SCALE * dot(Q[b,h,q,:], K[b,h,k,:])   (hd = 64 inner)
// Q/K are projected [B,S,D] with head h at columns [h*64, h*64+64).
// grid: (S/64, S/64, B*H), 256 threads, 4x4 per thread.
// ---------------------------------------------------------------------------
__global__ void scores_kernel(const float* __restrict__ Qp,
                              const float* __restrict__ Kp,
                              float* __restrict__ attn) {
    const int bh = blockIdx.z;
    const int b = bh / Hc, h = bh % Hc;
    const float* Qh = Qp + (size_t)b * Sc * Dc + h * HDc;
    const float* Kh = Kp + (size_t)b * Sc * Dc + h * HDc;
    float* out = attn + (size_t)bh * Sc * Sc;

    const int row0 = blockIdx.y * 64;  // q tile
    const int col0 = blockIdx.x * 64;  // k tile
    const int tx = threadIdx.x & 15;
    const int ty = threadIdx.x >> 4;

    __shared__ float As[16][64];
    __shared__ float Bs[16][64];
    float acc[4][4] = {};

    for (int k0 = 0; k0 < HDc; k0 += 16) {
        for (int i = threadIdx.x; i < 64 * 16; i += 256) {
            int r = i >> 4, c = i & 15;
            As[c][r] = Qh[(size_t)(row0 + r) * Dc + k0 + c];
            Bs[c][r] = Kh[(size_t)(col0 + r) * Dc + k0 + c];
        }
        __syncthreads();
#pragma unroll
        for (int kk = 0; kk < 16; kk++) {
            float a[4], bb[4];
#pragma unroll
            for (int i = 0; i < 4; i++) a[i] = As[kk][ty * 4 + i];
#pragma unroll
            for (int j = 0; j < 4; j++) bb[j] = Bs[kk][tx * 4 + j];
#pragma unroll
            for (int i = 0; i < 4; i++)
#pragma unroll
                for (int j = 0; j < 4; j++) acc[i][j] += a[i] * bb[j];
        }
        __syncthreads();
    }

#pragma unroll
    for (int i = 0; i < 4; i++)
#pragma unroll
        for (int j = 0; j < 4; j++)
            out[(size_t)(row0 + ty * 4 + i) * Sc + col0 + tx * 4 + j] =
                acc[i][j] * SCALEc;
}

// ---------------------------------------------------------------------------
// In-place row softmax over rows of length S=2048. One block (256 thr) per row;
// each thread holds 8 elements in registers (single read, single write).
// ---------------------------------------------------------------------------
__global__ void softmax_kernel(float* __restrict__ attn) {
    float* p = attn + (size_t)blockIdx.x * Sc;
    const int t = threadIdx.x;
    __shared__ float red[8];

    float v[8];
    float m = -3.4e38f;
#pragma unroll
    for (int i = 0; i < 8; i++) {
        v[i] = p[t + (i << 8)];
        m = fmaxf(m, v[i]);
    }
#pragma unroll
    for (int o = 16; o; o >>= 1) m = fmaxf(m, __shfl_xor_sync(0xffffffffu, m, o));
    if ((t & 31) == 0) red[t >> 5] = m;
    __syncthreads();
    if (t < 8) {
        float x = red[t];
#pragma unroll
        for (int o = 4; o; o >>= 1) x = fmaxf(x, __shfl_xor_sync(0xffu, x, o));
        red[t] = x;
    }
    __syncthreads();
    m = red[0];
    __syncthreads();

    float s = 0.f;
#pragma unroll
    for (int i = 0; i < 8; i++) {
        v[i] = __expf(v[i] - m);
        s += v[i];
    }
#pragma unroll
    for (int o = 16; o; o >>= 1) s += __shfl_xor_sync(0xffffffffu, s, o);
    if ((t & 31) == 0) red[t >> 5] = s;
    __syncthreads();
    if (t < 8) {
        float x = red[t];
#pragma unroll
        for (int o = 4; o; o >>= 1) x += __shfl_xor_sync(0xffu, x, o);
        red[t] = x;
    }
    __syncthreads();
    const float inv = 1.0f / red[0];
#pragma unroll
    for (int i = 0; i < 8; i++) p[t + (i << 8)] = v[i] * inv;
}

// ---------------------------------------------------------------------------
// ctx[b,q,h*64+d] = sum_k attn[b,h,q,k] * V[b,k,h*64+d]
// M=2048 (q), N=64 (d), K=2048. grid: (1, S/64, B*H).
// ---------------------------------------------------------------------------
__global__ void ctx_kernel(const float* __restrict__ attn,
                           const float* __restrict__ Vp,
                           float* __restrict__ ctx) {
    const int bh = blockIdx.z;
    const int b = bh / Hc, h = bh % Hc;
    const float* Arow = attn + (size_t)bh * Sc * Sc;
    const float* Vh = Vp + (size_t)b * Sc * Dc + h * HDc;

    const int row0 = blockIdx.y * 64;
    const int tx = threadIdx.x & 15;
    const int ty = threadIdx.x >> 4;

    __shared__ float As[16][64];
    __shared__ float Bs[16][64];
    float acc[4][4] = {};

    for (int k0 = 0; k0 < Sc; k0 += 16) {
        for (int i = threadIdx.x; i < 1024; i += 256) {
            int r = i >> 4, c = i & 15;
            As[c][r] = Arow[(size_t)(row0 + r) * Sc + k0 + c];
            int rr = i >> 6, cc = i & 63;
            Bs[rr][cc] = Vh[(size_t)(k0 + rr) * Dc + cc];
        }
        __syncthreads();
#pragma unroll
        for (int kk = 0; kk < 16; kk++) {
            float a[4], bb[4];
#pragma unroll
            for (int i = 0; i < 4; i++) a[i] = As[kk][ty * 4 + i];
#pragma unroll
            for (int j = 0; j < 4; j++) bb[j] = Bs[kk][tx * 4 + j];
#pragma unroll
            for (int i = 0; i < 4; i++)
#pragma unroll
                for (int j = 0; j < 4; j++) acc[i][j] += a[i] * bb[j];
        }
        __syncthreads();
    }

    float* outp = ctx + (size_t)(b * Sc + row0) * Dc + h * HDc;
#pragma unroll
    for (int i = 0; i < 4; i++)
#pragma unroll
        for (int j = 0; j < 4; j++)
            outp[(size_t)(ty * 4 + i) * Dc + tx * 4 + j] = acc[i][j];
}

// ---------------------------------------------------------------------------
// launch
// ---------------------------------------------------------------------------
extern "C" void kernel_launch(void* const* d_in, const int* in_sizes, int n_in,
                              void* d_out, int out_size) {
    const float* query = (const float*)d_in[0];
    const float* key   = (const float*)d_in[1];
    const float* value = (const float*)d_in[2];
    const float* Wq = (const float*)d_in[3];
    const float* bq = (const float*)d_in[4];
    const float* Wk = (const float*)d_in[5];
    const float* bk = (const float*)d_in[6];
    const float* Wv = (const float*)d_in[7];
    const float* bv = (const float*)d_in[8];
    const float* Wo = (const float*)d_in[9];
    const float* bo = (const float*)d_in[10];

    float* out = (float*)d_out;

    const size_t OUT_E  = (size_t)Bc * Sc * Dc;              // 4,194,304
    const size_t ATTN_E = (size_t)Bc * Hc * Sc * Sc;         // 134,217,728

    float* attn;
    if ((size_t)out_size >= OUT_E + ATTN_E) {
        attn = out + OUT_E;   // concatenated (output, attn_weights)
    } else {
        void* p = nullptr;
        cudaGetSymbolAddress(&p, g_attn_fb);
        attn = (float*)p;
    }

    float* Qp; { void* p; cudaGetSymbolAddress(&p, g_Q);   Qp = (float*)p; }
    float* Kp; { void* p; cudaGetSymbolAddress(&p, g_K);   Kp = (float*)p; }
    float* Vp; { void* p; cudaGetSymbolAddress(&p, g_V);   Vp = (float*)p; }
    float* Cx; { void* p; cudaGetSymbolAddress(&p, g_ctx); Cx = (float*)p; }

    const int M = Bc * Sc;   // 4096
    dim3 thr(256);
    dim3 gproj(Dc / 64, M / 64);               // (16, 64)

    gemm_bias_kernel<<<gproj, thr>>>(query, Wq, bq, Qp, M, Dc, Dc);
    gemm_bias_kernel<<<gproj, thr>>>(key,   Wk, bk, Kp, M, Dc, Dc);
    gemm_bias_kernel<<<gproj, thr>>>(value, Wv, bv, Vp, M, Dc, Dc);

    dim3 gscore(Sc / 64, Sc / 64, Bc * Hc);    // (32, 32, 32)
    scores_kernel<<<gscore, thr>>>(Qp, Kp, attn);

    softmax_kernel<<<Bc * Hc * Sc, thr>>>(attn);

    dim3 gctx(1, Sc / 64, Bc * Hc);            // (1, 32, 32)
    ctx_kernel<<<gctx, thr>>>(attn, Vp, Cx);

    gemm_bias_kernel<<<gproj, thr>>>(Cx, Wo, bo, out, M, Dc, Dc);
}

// round 2
// speedup vs baseline: 3.1558x; 3.1558x over previous
#include <cuda_runtime.h>
#include <cstdint>

#define Bc 2
#define Sc 2048
#define Dc 1024
#define Hc 16
#define HDc 64
#define BHc (Bc*Hc)
#define SCALEc 0.125f   // 64^-0.5

// ---- scratch (allocation-free rule: __device__ globals) --------------------
__device__ float g_Q[(size_t)Bc * Sc * Dc];
__device__ float g_K[(size_t)Bc * Sc * Dc];
__device__ float g_V[(size_t)Bc * Sc * Dc];
__device__ float g_ctx[(size_t)Bc * Sc * Dc];
__device__ float g_partial[(size_t)BHc * Sc * 16];   // per-(row, colblock) sums
__device__ float g_invsum[(size_t)BHc * Sc];
__device__ float g_attn_fb[(size_t)BHc * Sc * Sc];   // fallback if out only holds `output`

// ---- tf32 helpers ----------------------------------------------------------
__device__ __forceinline__ uint32_t f2tf(float x) {
    uint32_t r; asm("cvt.rna.tf32.f32 %0, %1;" : "=r"(r) : "f"(x)); return r;
}
__device__ __forceinline__ void mma8(float* d, const uint32_t* a, const uint32_t* b) {
    asm volatile(
        "mma.sync.aligned.m16n8k8.row.col.f32.tf32.tf32.f32 "
        "{%0,%1,%2,%3}, {%4,%5,%6,%7}, {%8,%9}, {%0,%1,%2,%3};\n"
        : "+f"(d[0]), "+f"(d[1]), "+f"(d[2]), "+f"(d[3])
        : "r"(a[0]), "r"(a[1]), "r"(a[2]), "r"(a[3]), "r"(b[0]), "r"(b[1]));
}

// ============================================================================
// GEMM + bias: C[M,N] = A[M,K] @ W[K,N] + b[N].  BM=128 BN=128 BK=16,
// 256 threads = 8 warps (2m x 4n), warp tile 64x32, mma m16n8k8 tf32.
// ============================================================================
__global__ __launch_bounds__(256)
void gemm_bias_tc(const float* __restrict__ A, const float* __restrict__ W,
                  const float* __restrict__ bias, float* __restrict__ C,
                  int M, int N, int K) {
    __shared__ uint32_t As[16][136];
    __shared__ uint32_t Bs[16][136];
    const int tid = threadIdx.x;
    const int lane = tid & 31, warp = tid >> 5;
    const int wm = warp >> 2, wn = warp & 3;
    const int row0 = blockIdx.y * 128, col0 = blockIdx.x * 128;
    const int r_lo = lane >> 2, c_lo = lane & 3;

    float acc[4][4][4] = {};

    for (int k0 = 0; k0 < K; k0 += 16) {
#pragma unroll
        for (int j = 0; j < 2; j++) {
            int f4 = tid * 2 + j;                 // 0..511
            int r = f4 >> 2, c4 = (f4 & 3) * 4;
            float4 v = *reinterpret_cast<const float4*>(&A[(size_t)(row0 + r) * K + k0 + c4]);
            As[c4 + 0][r] = f2tf(v.x); As[c4 + 1][r] = f2tf(v.y);
            As[c4 + 2][r] = f2tf(v.z); As[c4 + 3][r] = f2tf(v.w);
        }
#pragma unroll
        for (int j = 0; j < 2; j++) {
            int f4 = tid * 2 + j;
            int r = f4 >> 5, c4 = (f4 & 31) * 4;
            float4 v = *reinterpret_cast<const float4*>(&W[(size_t)(k0 + r) * N + col0 + c4]);
            Bs[r][c4 + 0] = f2tf(v.x); Bs[r][c4 + 1] = f2tf(v.y);
            Bs[r][c4 + 2] = f2tf(v.z); Bs[r][c4 + 3] = f2tf(v.w);
        }
        __syncthreads();
#pragma unroll
        for (int ks = 0; ks < 16; ks += 8) {
            uint32_t af[4][4], bf[4][2];
#pragma unroll
            for (int mt = 0; mt < 4; mt++) {
                int rb = wm * 64 + mt * 16 + r_lo;
                af[mt][0] = As[ks + c_lo][rb];
                af[mt][1] = As[ks + c_lo][rb + 8];
                af[mt][2] = As[ks + 4 + c_lo][rb];
                af[mt][3] = As[ks + 4 + c_lo][rb + 8];
            }
#pragma unroll
            for (int nt = 0; nt < 4; nt++) {
                int cb = wn * 32 + nt * 8 + r_lo;
                bf[nt][0] = Bs[ks + c_lo][cb];
                bf[nt][1] = Bs[ks + 4 + c_lo][cb];
            }
#pragma unroll
            for (int mt = 0; mt < 4; mt++)
#pragma unroll
                for (int nt = 0; nt < 4; nt++)
                    mma8(acc[mt][nt], af[mt], bf[nt]);
        }
        __syncthreads();
    }
#pragma unroll
    for (int mt = 0; mt < 4; mt++) {
        int row = row0 + wm * 64 + mt * 16 + r_lo;
#pragma unroll
        for (int nt = 0; nt < 4; nt++) {
            int col = col0 + wn * 32 + nt * 8 + c_lo * 2;
            float b0 = bias[col], b1 = bias[col + 1];
            C[(size_t)row * N + col]           = acc[mt][nt][0] + b0;
            C[(size_t)row * N + col + 1]       = acc[mt][nt][1] + b1;
            C[(size_t)(row + 8) * N + col]     = acc[mt][nt][2] + b0;
            C[(size_t)(row + 8) * N + col + 1] = acc[mt][nt][3] + b1;
        }
    }
}

// ============================================================================
// scores: expS[bh,q,k] = exp(SCALE * Q·K), unnormalized; also writes
// deterministic per-(row, colblock) partial sums. Tile 128x128, K=64.
// ============================================================================
__global__ __launch_bounds__(256)
void scores_tc(const float* __restrict__ Qp, const float* __restrict__ Kp,
               float* __restrict__ attn, float* __restrict__ partial) {
    __shared__ uint32_t As[16][136];
    __shared__ uint32_t Bs[16][136];
    __shared__ float ssum[128][4];
    const int bh = blockIdx.z;
    const int b = bh >> 4, h = bh & 15;
    const float* Qh = Qp + (size_t)b * Sc * Dc + h * HDc;
    const float* Kh = Kp + (size_t)b * Sc * Dc + h * HDc;
    float* outp = attn + (size_t)bh * Sc * Sc;
    const int tid = threadIdx.x, lane = tid & 31, warp = tid >> 5;
    const int wm = warp >> 2, wn = warp & 3;
    const int row0 = blockIdx.y * 128, col0 = blockIdx.x * 128;
    const int r_lo = lane >> 2, c_lo = lane & 3;

    float acc[4][4][4] = {};

    for (int k0 = 0; k0 < HDc; k0 += 16) {
#pragma unroll
        for (int j = 0; j < 2; j++) {
            int f4 = tid * 2 + j;
            int r = f4 >> 2, c4 = (f4 & 3) * 4;
            float4 va = *reinterpret_cast<const float4*>(&Qh[(size_t)(row0 + r) * Dc + k0 + c4]);
            As[c4 + 0][r] = f2tf(va.x); As[c4 + 1][r] = f2tf(va.y);
            As[c4 + 2][r] = f2tf(va.z); As[c4 + 3][r] = f2tf(va.w);
            float4 vb = *reinterpret_cast<const float4*>(&Kh[(size_t)(col0 + r) * Dc + k0 + c4]);
            Bs[c4 + 0][r] = f2tf(vb.x); Bs[c4 + 1][r] = f2tf(vb.y);
            Bs[c4 + 2][r] = f2tf(vb.z); Bs[c4 + 3][r] = f2tf(vb.w);
        }
        __syncthreads();
#pragma unroll
        for (int ks = 0; ks < 16; ks += 8) {
            uint32_t af[4][4], bf[4][2];
#pragma unroll
            for (int mt = 0; mt < 4; mt++) {
                int rb = wm * 64 + mt * 16 + r_lo;
                af[mt][0] = As[ks + c_lo][rb];
                af[mt][1] = As[ks + c_lo][rb + 8];
                af[mt][2] = As[ks + 4 + c_lo][rb];
                af[mt][3] = As[ks + 4 + c_lo][rb + 8];
            }
#pragma unroll
            for (int nt = 0; nt < 4; nt++) {
                int cb = wn * 32 + nt * 8 + r_lo;
                bf[nt][0] = Bs[ks + c_lo][cb];
                bf[nt][1] = Bs[ks + 4 + c_lo][cb];
            }
#pragma unroll
            for (int mt = 0; mt < 4; mt++)
#pragma unroll
                for (int nt = 0; nt < 4; nt++)
                    mma8(acc[mt][nt], af[mt], bf[nt]);
        }
        __syncthreads();
    }

    // epilogue: exp, store unnormalized, accumulate row sums
#pragma unroll
    for (int mt = 0; mt < 4; mt++) {
        float rs0 = 0.f, rs1 = 0.f;
        int row = row0 + wm * 64 + mt * 16 + r_lo;
#pragma unroll
        for (int nt = 0; nt < 4; nt++) {
            int col = col0 + wn * 32 + nt * 8 + c_lo * 2;
            float e0 = __expf(acc[mt][nt][0] * SCALEc);
            float e1 = __expf(acc[mt][nt][1] * SCALEc);
            float e2 = __expf(acc[mt][nt][2] * SCALEc);
            float e3 = __expf(acc[mt][nt][3] * SCALEc);
            outp[(size_t)row * Sc + col]           = e0;
            outp[(size_t)row * Sc + col + 1]       = e1;
            outp[(size_t)(row + 8) * Sc + col]     = e2;
            outp[(size_t)(row + 8) * Sc + col + 1] = e3;
            rs0 += e0 + e1;
            rs1 += e2 + e3;
        }
        rs0 += __shfl_xor_sync(0xffffffffu, rs0, 1);
        rs0 += __shfl_xor_sync(0xffffffffu, rs0, 2);
        rs1 += __shfl_xor_sync(0xffffffffu, rs1, 1);
        rs1 += __shfl_xor_sync(0xffffffffu, rs1, 2);
        if (c_lo == 0) {
            ssum[wm * 64 + mt * 16 + r_lo][wn]     = rs0;
            ssum[wm * 64 + mt * 16 + r_lo + 8][wn] = rs1;
        }
    }
    __syncthreads();
    if (tid < 128) {
        float s = ssum[tid][0] + ssum[tid][1] + ssum[tid][2] + ssum[tid][3];
        partial[((size_t)bh * Sc + row0 + tid) * 16 + blockIdx.x] = s;
    }
}

// deterministic row-sum finalize: invsum[row] = 1 / sum_j partial[row][j]
__global__ void invsum_k(const float* __restrict__ partial, float* __restrict__ invsum) {
    int i = blockIdx.x * 256 + threadIdx.x;   // 0..65535
    const float* p = partial + (size_t)i * 16;
    float s = 0.f;
#pragma unroll
    for (int j = 0; j < 16; j++) s += p[j];
    invsum[i] = 1.0f / s;
}

// ============================================================================
// ctx: normalize P on the fly (write final attn_weights) and P@V.
// BM=128, BN=64, BK=32. 256 threads = 8 warps (4m x 2n), warp tile 32x32.
// ============================================================================
__global__ __launch_bounds__(256)
void ctx_tc(float* __restrict__ attn, const float* __restrict__ Vp,
            const float* __restrict__ invsum, float* __restrict__ ctx) {
    __shared__ uint32_t As[32][136];
    __shared__ uint32_t Bs[32][72];
    __shared__ float invs[128];
    const int bh = blockIdx.y;
    const int b = bh >> 4, h = bh & 15;
    float* Pp = attn + (size_t)bh * Sc * Sc;
    const float* Vh = Vp + (size_t)b * Sc * Dc + h * HDc;
    const int tid = threadIdx.x, lane = tid & 31, warp = tid >> 5;
    const int wm = warp >> 1, wn = warp & 1;
    const int row0 = blockIdx.x * 128;
    const int r_lo = lane >> 2, c_lo = lane & 3;

    if (tid < 128) invs[tid] = invsum[(size_t)bh * Sc + row0 + tid];
    __syncthreads();

    float acc[2][4][4] = {};

    for (int k0 = 0; k0 < Sc; k0 += 32) {
        // P tile (128 x 32): read expS, normalize, write back, stage tf32
#pragma unroll
        for (int j = 0; j < 4; j++) {
            int f4 = tid + j * 256;               // 0..1023
            int r = f4 >> 3, c4 = (f4 & 7) * 4;
            size_t gidx = (size_t)(row0 + r) * Sc + k0 + c4;
            float4 v = *reinterpret_cast<const float4*>(&Pp[gidx]);
            float iv = invs[r];
            v.x *= iv; v.y *= iv; v.z *= iv; v.w *= iv;
            *reinterpret_cast<float4*>(&Pp[gidx]) = v;   // final attn_weights
            As[c4 + 0][r] = f2tf(v.x); As[c4 + 1][r] = f2tf(v.y);
            As[c4 + 2][r] = f2tf(v.z); As[c4 + 3][r] = f2tf(v.w);
        }
        // V tile (32 x 64)
#pragma unroll
        for (int j = 0; j < 2; j++) {
            int f4 = tid + j * 256;               // 0..511
            int r = f4 >> 4, c4 = (f4 & 15) * 4;
            float4 v = *reinterpret_cast<const float4*>(&Vh[(size_t)(k0 + r) * Dc + c4]);
            Bs[r][c4 + 0] = f2tf(v.x); Bs[r][c4 + 1] = f2tf(v.y);
            Bs[r][c4 + 2] = f2tf(v.z); Bs[r][c4 + 3] = f2tf(v.w);
        }
        __syncthreads();
#pragma unroll
        for (int ks = 0; ks < 32; ks += 8) {
            uint32_t af[2][4], bf[4][2];
#pragma unroll
            for (int mt = 0; mt < 2; mt++) {
                int rb = wm * 32 + mt * 16 + r_lo;
                af[mt][0] = As[ks + c_lo][rb];
                af[mt][1] = As[ks + c_lo][rb + 8];
                af[mt][2] = As[ks + 4 + c_lo][rb];
                af[mt][3] = As[ks + 4 + c_lo][rb + 8];
            }
#pragma unroll
            for (int nt = 0; nt < 4; nt++) {
                int cb = wn * 32 + nt * 8 + r_lo;
                bf[nt][0] = Bs[ks + c_lo][cb];
                bf[nt][1] = Bs[ks + 4 + c_lo][cb];
            }
#pragma unroll
            for (int mt = 0; mt < 2; mt++)
#pragma unroll
                for (int nt = 0; nt < 4; nt++)
                    mma8(acc[mt][nt], af[mt], bf[nt]);
        }
        __syncthreads();
    }

    float* outp = ctx + ((size_t)(b * Sc + row0)) * Dc + h * HDc;
#pragma unroll
    for (int mt = 0; mt < 2; mt++) {
        int row = wm * 32 + mt * 16 + r_lo;
#pragma unroll
        for (int nt = 0; nt < 4; nt++) {
            int col = wn * 32 + nt * 8 + c_lo * 2;
            outp[(size_t)row * Dc + col]           = acc[mt][nt][0];
            outp[(size_t)row * Dc + col + 1]       = acc[mt][nt][1];
            outp[(size_t)(row + 8) * Dc + col]     = acc[mt][nt][2];
            outp[(size_t)(row + 8) * Dc + col + 1] = acc[mt][nt][3];
        }
    }
}

// ---------------------------------------------------------------------------
extern "C" void kernel_launch(void* const* d_in, const int* in_sizes, int n_in,
                              void* d_out, int out_size) {
    const float* query = (const float*)d_in[0];
    const float* key   = (const float*)d_in[1];
    const float* value = (const float*)d_in[2];
    const float* Wq = (const float*)d_in[3];
    const float* bq = (const float*)d_in[4];
    const float* Wk = (const float*)d_in[5];
    const float* bk = (const float*)d_in[6];
    const float* Wv = (const float*)d_in[7];
    const float* bv = (const float*)d_in[8];
    const float* Wo = (const float*)d_in[9];
    const float* bo = (const float*)d_in[10];

    float* out = (float*)d_out;
    const size_t OUT_E  = (size_t)Bc * Sc * Dc;
    const size_t ATTN_E = (size_t)BHc * Sc * Sc;

    float* attn;
    if ((size_t)out_size >= OUT_E + ATTN_E) {
        attn = out + OUT_E;
    } else {
        void* p = nullptr; cudaGetSymbolAddress(&p, g_attn_fb); attn = (float*)p;
    }
    float* Qp;   { void* p; cudaGetSymbolAddress(&p, g_Q);       Qp = (float*)p; }
    float* Kp;   { void* p; cudaGetSymbolAddress(&p, g_K);       Kp = (float*)p; }
    float* Vp;   { void* p; cudaGetSymbolAddress(&p, g_V);       Vp = (float*)p; }
    float* Cx;   { void* p; cudaGetSymbolAddress(&p, g_ctx);     Cx = (float*)p; }
    float* part; { void* p; cudaGetSymbolAddress(&p, g_partial); part = (float*)p; }
    float* isum; { void* p; cudaGetSymbolAddress(&p, g_invsum);  isum = (float*)p; }

    const int M = Bc * Sc;                      // 4096
    dim3 thr(256);
    dim3 gproj(Dc / 128, M / 128);              // (8, 32)

    gemm_bias_tc<<<gproj, thr>>>(query, Wq, bq, Qp, M, Dc, Dc);
    gemm_bias_tc<<<gproj, thr>>>(key,   Wk, bk, Kp, M, Dc, Dc);
    gemm_bias_tc<<<gproj, thr>>>(value, Wv, bv, Vp, M, Dc, Dc);

    dim3 gscore(Sc / 128, Sc / 128, BHc);       // (16, 16, 32)
    scores_tc<<<gscore, thr>>>(Qp, Kp, attn, part);

    invsum_k<<<(BHc * Sc) / 256, thr>>>(part, isum);

    dim3 gctx(Sc / 128, BHc);                   // (16, 32)
    ctx_tc<<<gctx, thr>>>(attn, Vp, isum, Cx);

    gemm_bias_tc<<<gproj, thr>>>(Cx, Wo, bo, out, M, Dc, Dc);
}

// round 3
// speedup vs baseline: 3.5824x; 1.1352x over previous
#include <cuda_runtime.h>
#include <cstdint>

#define Bc 2
#define Sc 2048
#define Dc 1024
#define Hc 16
#define HDc 64
#define BHc (Bc*Hc)
#define SCALEc 0.125f   // 64^-0.5

// ---- scratch (allocation-free rule: __device__ globals) --------------------
__device__ float g_Q[(size_t)Bc * Sc * Dc];
__device__ float g_K[(size_t)Bc * Sc * Dc];
__device__ float g_V[(size_t)Bc * Sc * Dc];
__device__ float g_ctx[(size_t)Bc * Sc * Dc];
__device__ float g_invsum[(size_t)BHc * Sc];
__device__ float g_attn_fb[(size_t)BHc * Sc * Sc];   // fallback if out only holds `output`

// ---- tf32 helpers ----------------------------------------------------------
__device__ __forceinline__ uint32_t f2tf(float x) {
    uint32_t r; asm("cvt.rna.tf32.f32 %0, %1;" : "=r"(r) : "f"(x)); return r;
}
__device__ __forceinline__ void mma8(float* d, const uint32_t* a, const uint32_t* b) {
    asm volatile(
        "mma.sync.aligned.m16n8k8.row.col.f32.tf32.tf32.f32 "
        "{%0,%1,%2,%3}, {%4,%5,%6,%7}, {%8,%9}, {%0,%1,%2,%3};\n"
        : "+f"(d[0]), "+f"(d[1]), "+f"(d[2]), "+f"(d[3])
        : "r"(a[0]), "r"(a[1]), "r"(a[2]), "r"(a[3]), "r"(b[0]), "r"(b[1]));
}

// ============================================================================
// GEMM + bias, double-buffered: C[M,N] = A[M,K] @ W[K,N] + b[N].
// BM=BN=128, BK=16, 256 threads = 8 warps (2m x 4n), warp tile 64x32.
// ============================================================================
__global__ __launch_bounds__(256)
void gemm_bias_tc(const float* __restrict__ A, const float* __restrict__ W,
                  const float* __restrict__ bias, float* __restrict__ C,
                  int M, int N, int K) {
    __shared__ uint32_t As[2][16][136];
    __shared__ uint32_t Bs[2][16][136];
    const int tid = threadIdx.x;
    const int lane = tid & 31, warp = tid >> 5;
    const int wm = warp >> 2, wn = warp & 3;
    const int row0 = blockIdx.y * 128, col0 = blockIdx.x * 128;
    const int r_lo = lane >> 2, c_lo = lane & 3;

    // per-thread load coords
    const int fa0 = tid * 2, fa1 = tid * 2 + 1;
    const int ra0 = fa0 >> 2, ca0 = (fa0 & 3) * 4;
    const int ra1 = fa1 >> 2, ca1 = (fa1 & 3) * 4;
    const int rb0 = fa0 >> 5, cb0 = (fa0 & 31) * 4;
    const int rb1 = fa1 >> 5, cb1 = (fa1 & 31) * 4;

    float acc[4][4][4] = {};

    // prologue: stage 0
    {
        float4 v;
        v = *reinterpret_cast<const float4*>(&A[(size_t)(row0 + ra0) * K + ca0]);
        As[0][ca0+0][ra0]=f2tf(v.x); As[0][ca0+1][ra0]=f2tf(v.y);
        As[0][ca0+2][ra0]=f2tf(v.z); As[0][ca0+3][ra0]=f2tf(v.w);
        v = *reinterpret_cast<const float4*>(&A[(size_t)(row0 + ra1) * K + ca1]);
        As[0][ca1+0][ra1]=f2tf(v.x); As[0][ca1+1][ra1]=f2tf(v.y);
        As[0][ca1+2][ra1]=f2tf(v.z); As[0][ca1+3][ra1]=f2tf(v.w);
        v = *reinterpret_cast<const float4*>(&W[(size_t)rb0 * N + col0 + cb0]);
        Bs[0][rb0][cb0+0]=f2tf(v.x); Bs[0][rb0][cb0+1]=f2tf(v.y);
        Bs[0][rb0][cb0+2]=f2tf(v.z); Bs[0][rb0][cb0+3]=f2tf(v.w);
        v = *reinterpret_cast<const float4*>(&W[(size_t)rb1 * N + col0 + cb1]);
        Bs[0][rb1][cb1+0]=f2tf(v.x); Bs[0][rb1][cb1+1]=f2tf(v.y);
        Bs[0][rb1][cb1+2]=f2tf(v.z); Bs[0][rb1][cb1+3]=f2tf(v.w);
    }
    __syncthreads();

    const int nk = K >> 4;
    float4 pa0, pa1, pb0, pb1;
    for (int kt = 0; kt < nk; kt++) {
        const int s = kt & 1;
        const int k0n = (kt + 1) << 4;
        if (kt + 1 < nk) {
            pa0 = *reinterpret_cast<const float4*>(&A[(size_t)(row0 + ra0) * K + k0n + ca0]);
            pa1 = *reinterpret_cast<const float4*>(&A[(size_t)(row0 + ra1) * K + k0n + ca1]);
            pb0 = *reinterpret_cast<const float4*>(&W[(size_t)(k0n + rb0) * N + col0 + cb0]);
            pb1 = *reinterpret_cast<const float4*>(&W[(size_t)(k0n + rb1) * N + col0 + cb1]);
        }
#pragma unroll
        for (int ks = 0; ks < 16; ks += 8) {
            uint32_t af[4][4], bf[4][2];
#pragma unroll
            for (int mt = 0; mt < 4; mt++) {
                int rb = wm * 64 + mt * 16 + r_lo;
                af[mt][0] = As[s][ks + c_lo][rb];
                af[mt][1] = As[s][ks + c_lo][rb + 8];
                af[mt][2] = As[s][ks + 4 + c_lo][rb];
                af[mt][3] = As[s][ks + 4 + c_lo][rb + 8];
            }
#pragma unroll
            for (int nt = 0; nt < 4; nt++) {
                int cb = wn * 32 + nt * 8 + r_lo;
                bf[nt][0] = Bs[s][ks + c_lo][cb];
                bf[nt][1] = Bs[s][ks + 4 + c_lo][cb];
            }
#pragma unroll
            for (int mt = 0; mt < 4; mt++)
#pragma unroll
                for (int nt = 0; nt < 4; nt++)
                    mma8(acc[mt][nt], af[mt], bf[nt]);
        }
        if (kt + 1 < nk) {
            const int d = s ^ 1;
            As[d][ca0+0][ra0]=f2tf(pa0.x); As[d][ca0+1][ra0]=f2tf(pa0.y);
            As[d][ca0+2][ra0]=f2tf(pa0.z); As[d][ca0+3][ra0]=f2tf(pa0.w);
            As[d][ca1+0][ra1]=f2tf(pa1.x); As[d][ca1+1][ra1]=f2tf(pa1.y);
            As[d][ca1+2][ra1]=f2tf(pa1.z); As[d][ca1+3][ra1]=f2tf(pa1.w);
            Bs[d][rb0][cb0+0]=f2tf(pb0.x); Bs[d][rb0][cb0+1]=f2tf(pb0.y);
            Bs[d][rb0][cb0+2]=f2tf(pb0.z); Bs[d][rb0][cb0+3]=f2tf(pb0.w);
            Bs[d][rb1][cb1+0]=f2tf(pb1.x); Bs[d][rb1][cb1+1]=f2tf(pb1.y);
            Bs[d][rb1][cb1+2]=f2tf(pb1.z); Bs[d][rb1][cb1+3]=f2tf(pb1.w);
        }
        __syncthreads();
    }

#pragma unroll
    for (int mt = 0; mt < 4; mt++) {
        int row = row0 + wm * 64 + mt * 16 + r_lo;
#pragma unroll
        for (int nt = 0; nt < 4; nt++) {
            int col = col0 + wn * 32 + nt * 8 + c_lo * 2;
            float b0 = bias[col], b1 = bias[col + 1];
            C[(size_t)row * N + col]           = acc[mt][nt][0] + b0;
            C[(size_t)row * N + col + 1]       = acc[mt][nt][1] + b1;
            C[(size_t)(row + 8) * N + col]     = acc[mt][nt][2] + b0;
            C[(size_t)(row + 8) * N + col + 1] = acc[mt][nt][3] + b1;
        }
    }
}

// ============================================================================
// Fused attention: per (q-tile 128, bh) block, loop over all 16 k-tiles:
//   S = Q K^T (mma) -> E = exp(S*scale) (regs) -> sE smem tile
//   -> write unnormalized E to gmem (coalesced) -> U += E @ V (mma from smem)
// After loop: rowsum (exact, in-register across full row) -> write inv[row],
// write final ctx = U * inv. Normalization of attn done by norm_k afterwards.
// ============================================================================
#define OFF_Q 0
#define OFF_K 8448
#define OFF_V 16896
#define OFF_E 26112
#define OFF_R 43008
#define SMEM_U32 43520            // * 4 = 174080 bytes

__global__ __launch_bounds__(256)
void fused_attn(const float* __restrict__ Qp, const float* __restrict__ Kp,
                const float* __restrict__ Vp, float* __restrict__ attn,
                float* __restrict__ invg, float* __restrict__ ctx) {
    extern __shared__ uint32_t sm[];
    uint32_t* sQ = sm + OFF_Q;            // [64][132]  k-major: sQ[k*132 + row]
    uint32_t* sK = sm + OFF_K;            // [64][132]  k-major: sK[k*132 + col]
    uint32_t* sV = sm + OFF_V;            // [128][72]  sV[k*72 + col]
    float*    sE = (float*)(sm + OFF_E);  // [128][132] row-major
    float*    red = (float*)(sm + OFF_R); // [128][4]

    const int bh = blockIdx.y, b = bh >> 4, h = bh & 15;
    const int row0 = blockIdx.x * 128;
    const float* Qh = Qp + (size_t)b * Sc * Dc + h * HDc;
    const float* Kh = Kp + (size_t)b * Sc * Dc + h * HDc;
    const float* Vh = Vp + (size_t)b * Sc * Dc + h * HDc;
    float* outp = attn + (size_t)bh * Sc * Sc;

    const int tid = threadIdx.x, lane = tid & 31, warp = tid >> 5;
    const int wmS = warp >> 2, wnS = warp & 3;   // S phase: 2m x 4n, tile 64x32
    const int wmP = warp >> 1, wnP = warp & 1;   // PV phase: 4m x 2n, tile 32x32
    const int r_lo = lane >> 2, c_lo = lane & 3;

    // stage Q once
#pragma unroll
    for (int j = 0; j < 8; j++) {
        int f4 = tid + j * 256; int r = f4 >> 4, c4 = (f4 & 15) * 4;
        float4 v = *reinterpret_cast<const float4*>(&Qh[(size_t)(row0 + r) * Dc + c4]);
        sQ[(c4+0)*132 + r] = f2tf(v.x); sQ[(c4+1)*132 + r] = f2tf(v.y);
        sQ[(c4+2)*132 + r] = f2tf(v.z); sQ[(c4+3)*132 + r] = f2tf(v.w);
    }

    float accU[2][4][4] = {};
    float rs[4][2] = {};

    for (int kt = 0; kt < 16; kt++) {
        const int k0 = kt * 128;
        // K tile (k-major staging)
#pragma unroll
        for (int j = 0; j < 8; j++) {
            int f4 = tid + j * 256; int r = f4 >> 4, c4 = (f4 & 15) * 4;
            float4 v = *reinterpret_cast<const float4*>(&Kh[(size_t)(k0 + r) * Dc + c4]);
            sK[(c4+0)*132 + r] = f2tf(v.x); sK[(c4+1)*132 + r] = f2tf(v.y);
            sK[(c4+2)*132 + r] = f2tf(v.z); sK[(c4+3)*132 + r] = f2tf(v.w);
        }
        // V tile (row-major staging)
#pragma unroll
        for (int j = 0; j < 8; j++) {
            int f4 = tid + j * 256; int r = f4 >> 4, c4 = (f4 & 15) * 4;
            float4 v = *reinterpret_cast<const float4*>(&Vh[(size_t)(k0 + r) * Dc + c4]);
            sV[r*72 + c4+0] = f2tf(v.x); sV[r*72 + c4+1] = f2tf(v.y);
            sV[r*72 + c4+2] = f2tf(v.z); sV[r*72 + c4+3] = f2tf(v.w);
        }
        __syncthreads();

        // ---- S = Q K^T (128x128, k=64) ----
        float accS[4][4][4] = {};
#pragma unroll
        for (int ks = 0; ks < 64; ks += 8) {
            uint32_t af[4][4], bf[4][2];
#pragma unroll
            for (int mt = 0; mt < 4; mt++) {
                int rb = wmS * 64 + mt * 16 + r_lo;
                af[mt][0] = sQ[(ks + c_lo)*132 + rb];
                af[mt][1] = sQ[(ks + c_lo)*132 + rb + 8];
                af[mt][2] = sQ[(ks + 4 + c_lo)*132 + rb];
                af[mt][3] = sQ[(ks + 4 + c_lo)*132 + rb + 8];
            }
#pragma unroll
            for (int nt = 0; nt < 4; nt++) {
                int cb = wnS * 32 + nt * 8 + r_lo;
                bf[nt][0] = sK[(ks + c_lo)*132 + cb];
                bf[nt][1] = sK[(ks + 4 + c_lo)*132 + cb];
            }
#pragma unroll
            for (int mt = 0; mt < 4; mt++)
#pragma unroll
                for (int nt = 0; nt < 4; nt++)
                    mma8(accS[mt][nt], af[mt], bf[nt]);
        }

        // ---- exp + rowsum + stage E ----
#pragma unroll
        for (int mt = 0; mt < 4; mt++) {
            int rw = wmS * 64 + mt * 16 + r_lo;
#pragma unroll
            for (int nt = 0; nt < 4; nt++) {
                int cl = wnS * 32 + nt * 8 + c_lo * 2;
                float e0 = __expf(accS[mt][nt][0] * SCALEc);
                float e1 = __expf(accS[mt][nt][1] * SCALEc);
                float e2 = __expf(accS[mt][nt][2] * SCALEc);
                float e3 = __expf(accS[mt][nt][3] * SCALEc);
                rs[mt][0] += e0 + e1;
                rs[mt][1] += e2 + e3;
                *reinterpret_cast<float2*>(&sE[rw*132 + cl])     = make_float2(e0, e1);
                *reinterpret_cast<float2*>(&sE[(rw+8)*132 + cl]) = make_float2(e2, e3);
            }
        }
        __syncthreads();

        // ---- unnormalized E -> gmem (coalesced rows) ----
#pragma unroll
        for (int j = 0; j < 16; j++) {
            int f4 = j * 256 + tid; int r = f4 >> 5, c4 = (f4 & 31) * 4;
            float4 v = *reinterpret_cast<const float4*>(&sE[r*132 + c4]);
            *reinterpret_cast<float4*>(&outp[(size_t)(row0 + r) * Sc + k0 + c4]) = v;
        }

        // ---- U += E @ V (128x64, k=128) ----
#pragma unroll
        for (int ks = 0; ks < 128; ks += 8) {
            uint32_t af[2][4], bf[4][2];
#pragma unroll
            for (int mt = 0; mt < 2; mt++) {
                int rb = wmP * 32 + mt * 16 + r_lo;
                af[mt][0] = f2tf(sE[rb*132 + ks + c_lo]);
                af[mt][1] = f2tf(sE[(rb+8)*132 + ks + c_lo]);
                af[mt][2] = f2tf(sE[rb*132 + ks + 4 + c_lo]);
                af[mt][3] = f2tf(sE[(rb+8)*132 + ks + 4 + c_lo]);
            }
#pragma unroll
            for (int nt = 0; nt < 4; nt++) {
                int cb = wnP * 32 + nt * 8 + r_lo;
                bf[nt][0] = sV[(ks + c_lo)*72 + cb];
                bf[nt][1] = sV[(ks + 4 + c_lo)*72 + cb];
            }
#pragma unroll
            for (int mt = 0; mt < 2; mt++)
#pragma unroll
                for (int nt = 0; nt < 4; nt++)
                    mma8(accU[mt][nt], af[mt], bf[nt]);
        }
        __syncthreads();
    }

    // ---- rowsum -> inv ----
#pragma unroll
    for (int mt = 0; mt < 4; mt++)
#pragma unroll
        for (int h2 = 0; h2 < 2; h2++) {
            float v = rs[mt][h2];
            v += __shfl_xor_sync(0xffffffffu, v, 1);
            v += __shfl_xor_sync(0xffffffffu, v, 2);
            if (c_lo == 0) red[(wmS*64 + mt*16 + r_lo + h2*8)*4 + wnS] = v;
        }
    __syncthreads();
    if (tid < 128) {
        float s = red[tid*4] + red[tid*4+1] + red[tid*4+2] + red[tid*4+3];
        float iv = 1.0f / s;
        invg[(size_t)bh * Sc + row0 + tid] = iv;
        red[tid*4] = iv;
    }
    __syncthreads();

    // ---- ctx = U * inv ----
    float* cp = ctx + (size_t)(b * Sc + row0) * Dc + h * HDc;
#pragma unroll
    for (int mt = 0; mt < 2; mt++) {
        int rw = wmP * 32 + mt * 16 + r_lo;
        float iv0 = red[rw*4], iv1 = red[(rw+8)*4];
#pragma unroll
        for (int nt = 0; nt < 4; nt++) {
            int cl = wnP * 32 + nt * 8 + c_lo * 2;
            cp[(size_t)rw * Dc + cl]         = accU[mt][nt][0] * iv0;
            cp[(size_t)rw * Dc + cl + 1]     = accU[mt][nt][1] * iv0;
            cp[(size_t)(rw+8) * Dc + cl]     = accU[mt][nt][2] * iv1;
            cp[(size_t)(rw+8) * Dc + cl + 1] = accU[mt][nt][3] * iv1;
        }
    }
}

// ============================================================================
// normalize attn in place: attn[row, :] *= inv[row]   (pure bandwidth)
// ============================================================================
__global__ void norm_k(float4* __restrict__ attn4, const float* __restrict__ inv) {
    const size_t total = (size_t)BHc * Sc * Sc / 4;
    size_t i = (size_t)blockIdx.x * blockDim.x + threadIdx.x;
    const size_t stride = (size_t)gridDim.x * blockDim.x;
    for (; i < total; i += stride) {
        float s = __ldg(&inv[i >> 9]);     // 512 float4 per row
        float4 v = attn4[i];
        v.x *= s; v.y *= s; v.z *= s; v.w *= s;
        attn4[i] = v;
    }
}

// ---------------------------------------------------------------------------
extern "C" void kernel_launch(void* const* d_in, const int* in_sizes, int n_in,
                              void* d_out, int out_size) {
    const float* query = (const float*)d_in[0];
    const float* key   = (const float*)d_in[1];
    const float* value = (const float*)d_in[2];
    const float* Wq = (const float*)d_in[3];
    const float* bq = (const float*)d_in[4];
    const float* Wk = (const float*)d_in[5];
    const float* bk = (const float*)d_in[6];
    const float* Wv = (const float*)d_in[7];
    const float* bv = (const float*)d_in[8];
    const float* Wo = (const float*)d_in[9];
    const float* bo = (const float*)d_in[10];

    float* out = (float*)d_out;
    const size_t OUT_E  = (size_t)Bc * Sc * Dc;
    const size_t ATTN_E = (size_t)BHc * Sc * Sc;

    float* attn;
    if ((size_t)out_size >= OUT_E + ATTN_E) {
        attn = out + OUT_E;
    } else {
        void* p = nullptr; cudaGetSymbolAddress(&p, g_attn_fb); attn = (float*)p;
    }
    float* Qp;   { void* p; cudaGetSymbolAddress(&p, g_Q);      Qp = (float*)p; }
    float* Kp;   { void* p; cudaGetSymbolAddress(&p, g_K);      Kp = (float*)p; }
    float* Vp;   { void* p; cudaGetSymbolAddress(&p, g_V);      Vp = (float*)p; }
    float* Cx;   { void* p; cudaGetSymbolAddress(&p, g_ctx);    Cx = (float*)p; }
    float* isum; { void* p; cudaGetSymbolAddress(&p, g_invsum); isum = (float*)p; }

    cudaFuncSetAttribute(fused_attn, cudaFuncAttributeMaxDynamicSharedMemorySize,
                         SMEM_U32 * 4);

    const int M = Bc * Sc;                      // 4096
    dim3 thr(256);
    dim3 gproj(Dc / 128, M / 128);              // (8, 32)

    gemm_bias_tc<<<gproj, thr>>>(query, Wq, bq, Qp, M, Dc, Dc);
    gemm_bias_tc<<<gproj, thr>>>(key,   Wk, bk, Kp, M, Dc, Dc);
    gemm_bias_tc<<<gproj, thr>>>(value, Wv, bv, Vp, M, Dc, Dc);

    dim3 gfa(Sc / 128, BHc);                    // (16, 32)
    fused_attn<<<gfa, thr, SMEM_U32 * 4>>>(Qp, Kp, Vp, attn, isum, Cx);

    norm_k<<<4736, 256>>>((float4*)attn, isum);

    gemm_bias_tc<<<gproj, thr>>>(Cx, Wo, bo, out, M, Dc, Dc);
}

// round 4
// speedup vs baseline: 4.1074x; 1.1465x over previous
#include <cuda_runtime.h>
#include <cstdint>

#define Bc 2
#define Sc 2048
#define Dc 1024
#define Hc 16
#define HDc 64
#define BHc (Bc*Hc)
#define SCALEc 0.125f   // 64^-0.5

// ---- scratch (allocation-free rule: __device__ globals) --------------------
__device__ float g_Q[(size_t)Bc * Sc * Dc];
__device__ float g_K[(size_t)Bc * Sc * Dc];
__device__ float g_V[(size_t)Bc * Sc * Dc];
__device__ float g_ctx[(size_t)Bc * Sc * Dc];
__device__ float g_invsum[(size_t)BHc * Sc];
__device__ float g_attn_fb[(size_t)BHc * Sc * Sc];   // fallback if out only holds `output`

// ---- helpers ----------------------------------------------------------------
__device__ __forceinline__ uint32_t f2tf(float x) {
    uint32_t r; asm("cvt.rna.tf32.f32 %0, %1;" : "=r"(r) : "f"(x)); return r;
}
__device__ __forceinline__ void mma8(float* d, const uint32_t* a, const uint32_t* b) {
    asm volatile(
        "mma.sync.aligned.m16n8k8.row.col.f32.tf32.tf32.f32 "
        "{%0,%1,%2,%3}, {%4,%5,%6,%7}, {%8,%9}, {%0,%1,%2,%3};\n"
        : "+f"(d[0]), "+f"(d[1]), "+f"(d[2]), "+f"(d[3])
        : "r"(a[0]), "r"(a[1]), "r"(a[2]), "r"(a[3]), "r"(b[0]), "r"(b[1]));
}
__device__ __forceinline__ uint32_t smem_u32(const void* p) {
    uint32_t r;
    asm("{ .reg .u64 t; cvta.to.shared.u64 t, %1; cvt.u32.u64 %0, t; }"
        : "=r"(r) : "l"(p));
    return r;
}
__device__ __forceinline__ void cpa16(uint32_t saddr, const void* g) {
    asm volatile("cp.async.cg.shared.global [%0], [%1], 16;" :: "r"(saddr), "l"(g));
}
__device__ __forceinline__ void cpa_commit() { asm volatile("cp.async.commit_group;"); }
__device__ __forceinline__ void cpa_wait0()  { asm volatile("cp.async.wait_group 0;"); }

// ============================================================================
// GEMM + bias, double-buffered tf32 mma (unchanged from round 3 — works).
// ============================================================================
__global__ __launch_bounds__(256)
void gemm_bias_tc(const float* __restrict__ A, const float* __restrict__ W,
                  const float* __restrict__ bias, float* __restrict__ C,
                  int M, int N, int K) {
    __shared__ uint32_t As[2][16][136];
    __shared__ uint32_t Bs[2][16][136];
    const int tid = threadIdx.x;
    const int lane = tid & 31, warp = tid >> 5;
    const int wm = warp >> 2, wn = warp & 3;
    const int row0 = blockIdx.y * 128, col0 = blockIdx.x * 128;
    const int r_lo = lane >> 2, c_lo = lane & 3;

    const int fa0 = tid * 2, fa1 = tid * 2 + 1;
    const int ra0 = fa0 >> 2, ca0 = (fa0 & 3) * 4;
    const int ra1 = fa1 >> 2, ca1 = (fa1 & 3) * 4;
    const int rb0 = fa0 >> 5, cb0 = (fa0 & 31) * 4;
    const int rb1 = fa1 >> 5, cb1 = (fa1 & 31) * 4;

    float acc[4][4][4] = {};

    {
        float4 v;
        v = *reinterpret_cast<const float4*>(&A[(size_t)(row0 + ra0) * K + ca0]);
        As[0][ca0+0][ra0]=f2tf(v.x); As[0][ca0+1][ra0]=f2tf(v.y);
        As[0][ca0+2][ra0]=f2tf(v.z); As[0][ca0+3][ra0]=f2tf(v.w);
        v = *reinterpret_cast<const float4*>(&A[(size_t)(row0 + ra1) * K + ca1]);
        As[0][ca1+0][ra1]=f2tf(v.x); As[0][ca1+1][ra1]=f2tf(v.y);
        As[0][ca1+2][ra1]=f2tf(v.z); As[0][ca1+3][ra1]=f2tf(v.w);
        v = *reinterpret_cast<const float4*>(&W[(size_t)rb0 * N + col0 + cb0]);
        Bs[0][rb0][cb0+0]=f2tf(v.x); Bs[0][rb0][cb0+1]=f2tf(v.y);
        Bs[0][rb0][cb0+2]=f2tf(v.z); Bs[0][rb0][cb0+3]=f2tf(v.w);
        v = *reinterpret_cast<const float4*>(&W[(size_t)rb1 * N + col0 + cb1]);
        Bs[0][rb1][cb1+0]=f2tf(v.x); Bs[0][rb1][cb1+1]=f2tf(v.y);
        Bs[0][rb1][cb1+2]=f2tf(v.z); Bs[0][rb1][cb1+3]=f2tf(v.w);
    }
    __syncthreads();

    const int nk = K >> 4;
    float4 pa0, pa1, pb0, pb1;
    for (int kt = 0; kt < nk; kt++) {
        const int s = kt & 1;
        const int k0n = (kt + 1) << 4;
        if (kt + 1 < nk) {
            pa0 = *reinterpret_cast<const float4*>(&A[(size_t)(row0 + ra0) * K + k0n + ca0]);
            pa1 = *reinterpret_cast<const float4*>(&A[(size_t)(row0 + ra1) * K + k0n + ca1]);
            pb0 = *reinterpret_cast<const float4*>(&W[(size_t)(k0n + rb0) * N + col0 + cb0]);
            pb1 = *reinterpret_cast<const float4*>(&W[(size_t)(k0n + rb1) * N + col0 + cb1]);
        }
#pragma unroll
        for (int ks = 0; ks < 16; ks += 8) {
            uint32_t af[4][4], bf[4][2];
#pragma unroll
            for (int mt = 0; mt < 4; mt++) {
                int rb = wm * 64 + mt * 16 + r_lo;
                af[mt][0] = As[s][ks + c_lo][rb];
                af[mt][1] = As[s][ks + c_lo][rb + 8];
                af[mt][2] = As[s][ks + 4 + c_lo][rb];
                af[mt][3] = As[s][ks + 4 + c_lo][rb + 8];
            }
#pragma unroll
            for (int nt = 0; nt < 4; nt++) {
                int cb = wn * 32 + nt * 8 + r_lo;
                bf[nt][0] = Bs[s][ks + c_lo][cb];
                bf[nt][1] = Bs[s][ks + 4 + c_lo][cb];
            }
#pragma unroll
            for (int mt = 0; mt < 4; mt++)
#pragma unroll
                for (int nt = 0; nt < 4; nt++)
                    mma8(acc[mt][nt], af[mt], bf[nt]);
        }
        if (kt + 1 < nk) {
            const int d = s ^ 1;
            As[d][ca0+0][ra0]=f2tf(pa0.x); As[d][ca0+1][ra0]=f2tf(pa0.y);
            As[d][ca0+2][ra0]=f2tf(pa0.z); As[d][ca0+3][ra0]=f2tf(pa0.w);
            As[d][ca1+0][ra1]=f2tf(pa1.x); As[d][ca1+1][ra1]=f2tf(pa1.y);
            As[d][ca1+2][ra1]=f2tf(pa1.z); As[d][ca1+3][ra1]=f2tf(pa1.w);
            Bs[d][rb0][cb0+0]=f2tf(pb0.x); Bs[d][rb0][cb0+1]=f2tf(pb0.y);
            Bs[d][rb0][cb0+2]=f2tf(pb0.z); Bs[d][rb0][cb0+3]=f2tf(pb0.w);
            Bs[d][rb1][cb1+0]=f2tf(pb1.x); Bs[d][rb1][cb1+1]=f2tf(pb1.y);
            Bs[d][rb1][cb1+2]=f2tf(pb1.z); Bs[d][rb1][cb1+3]=f2tf(pb1.w);
        }
        __syncthreads();
    }

#pragma unroll
    for (int mt = 0; mt < 4; mt++) {
        int row = row0 + wm * 64 + mt * 16 + r_lo;
#pragma unroll
        for (int nt = 0; nt < 4; nt++) {
            int col = col0 + wn * 32 + nt * 8 + c_lo * 2;
            float b0 = bias[col], b1 = bias[col + 1];
            C[(size_t)row * N + col]           = acc[mt][nt][0] + b0;
            C[(size_t)row * N + col + 1]       = acc[mt][nt][1] + b1;
            C[(size_t)(row + 8) * N + col]     = acc[mt][nt][2] + b0;
            C[(size_t)(row + 8) * N + col + 1] = acc[mt][nt][3] + b1;
        }
    }
}

// ============================================================================
// Fused attention v3: 512 threads (16 warps, 8m x 2n). Q in registers,
// K/V cp.async double-buffered, E straight regs->gmem, PV A-fragments via
// shuffle transpose of S accumulators (no sE smem). One sync per k-tile.
// ============================================================================
// float offsets inside dynamic smem
#define FK0 0
#define FK1 8704
#define FV0 17408
#define FV1 26112
#define FRED 34816          // 256 floats: [row][wn]
#define FRED2 35072         // 128 floats: inv per row
#define FTOT 35200          // *4 = 140800 bytes

__global__ __launch_bounds__(512)
void fused_attn(const float* __restrict__ Qp, const float* __restrict__ Kp,
                const float* __restrict__ Vp, float* __restrict__ attn,
                float* __restrict__ invg, float* __restrict__ ctx) {
    extern __shared__ float smf[];
    const uint32_t sbase = smem_u32(smf);

    const int bh = blockIdx.y, b = bh >> 4, h = bh & 15;
    const int row0 = blockIdx.x * 128;
    const float* Qh = Qp + (size_t)b * Sc * Dc + h * HDc;
    const float* Kh = Kp + (size_t)b * Sc * Dc + h * HDc;
    const float* Vh = Vp + (size_t)b * Sc * Dc + h * HDc;
    float* outp = attn + (size_t)bh * Sc * Sc;

    const int tid = threadIdx.x, lane = tid & 31, warp = tid >> 5;
    const int wm = warp >> 1, wn = warp & 1;   // 8m x 2n
    const int g = lane >> 2, c = lane & 3;

    // per-thread cp.async coords: 4 chunks of 16B per tile per thread
    const int ldr0 = tid >> 4;                 // rows 0..31 (+32 per i)
    const int ldc4 = (tid & 15) * 4;

    // ---- issue first K/V tile ----
    {
        const float* gk = Kh;
        const float* gv = Vh;
#pragma unroll
        for (int i = 0; i < 4; i++) {
            int r = ldr0 + i * 32;
            cpa16(sbase + (uint32_t)(FK0 + r * 68 + ldc4) * 4, gk + (size_t)r * Dc + ldc4);
            cpa16(sbase + (uint32_t)(FV0 + r * 68 + ldc4) * 4, gv + (size_t)r * Dc + ldc4);
        }
        cpa_commit();
    }

    // ---- Q fragments in registers (rna tf32), rows [row0+16wm, +16) ----
    uint32_t qf[8][4];
    {
        const int qr = row0 + wm * 16;
#pragma unroll
        for (int s8 = 0; s8 < 8; s8++) {
            qf[s8][0] = f2tf(Qh[(size_t)(qr + g)     * Dc + s8 * 8 + c]);
            qf[s8][1] = f2tf(Qh[(size_t)(qr + g + 8) * Dc + s8 * 8 + c]);
            qf[s8][2] = f2tf(Qh[(size_t)(qr + g)     * Dc + s8 * 8 + c + 4]);
            qf[s8][3] = f2tf(Qh[(size_t)(qr + g + 8) * Dc + s8 * 8 + c + 4]);
        }
    }

    cpa_wait0();
    __syncthreads();

    float accU[8][4] = {};      // 16 rows x 64 cols partial (this warp's k-strip)
    float rs0 = 0.f, rs1 = 0.f; // row sums for rows g, g+8 (this warp's strip)

    const int src1 = (lane & ~3) | (c >> 1);
    const int src2 = src1 + 2;
    const bool odd = (c & 1);

    for (int kt = 0; kt < 16; kt++) {
        const int s = kt & 1;
        if (kt + 1 < 16) {
            const float* gk = Kh + (size_t)((kt + 1) * 128) * Dc;
            const float* gv = Vh + (size_t)((kt + 1) * 128) * Dc;
            const int KD = s ? FK0 : FK1;
            const int VD = s ? FV0 : FV1;
#pragma unroll
            for (int i = 0; i < 4; i++) {
                int r = ldr0 + i * 32;
                cpa16(sbase + (uint32_t)(KD + r * 68 + ldc4) * 4, gk + (size_t)r * Dc + ldc4);
                cpa16(sbase + (uint32_t)(VD + r * 68 + ldc4) * 4, gv + (size_t)r * Dc + ldc4);
            }
            cpa_commit();
        }
        const float* sK = smf + (s ? FK1 : FK0);
        const float* sV = smf + (s ? FV1 : FV0);
        const int k0 = kt * 128;

#pragma unroll
        for (int half = 0; half < 2; half++) {
            const int colbase = wn * 64 + half * 32;

            // ---- S = Q K^T for this 16x32 strip ----
            float accS[4][4] = {};
#pragma unroll
            for (int s8 = 0; s8 < 8; s8++) {
                uint32_t bf[4][2];
#pragma unroll
                for (int nt = 0; nt < 4; nt++) {
                    int kc = colbase + nt * 8 + g;
                    bf[nt][0] = __float_as_uint(sK[kc * 68 + s8 * 8 + c]);
                    bf[nt][1] = __float_as_uint(sK[kc * 68 + s8 * 8 + c + 4]);
                }
#pragma unroll
                for (int nt = 0; nt < 4; nt++)
                    mma8(accS[nt], qf[s8], bf[nt]);
            }

            // ---- exp + rowsum + unnormalized E -> gmem ----
            const int grow = row0 + wm * 16 + g;
#pragma unroll
            for (int nt = 0; nt < 4; nt++) {
                float e0 = __expf(accS[nt][0] * SCALEc);
                float e1 = __expf(accS[nt][1] * SCALEc);
                float e2 = __expf(accS[nt][2] * SCALEc);
                float e3 = __expf(accS[nt][3] * SCALEc);
                rs0 += e0 + e1; rs1 += e2 + e3;
                int gcol = k0 + colbase + nt * 8 + c * 2;
                *reinterpret_cast<float2*>(&outp[(size_t)grow * Sc + gcol])       = make_float2(e0, e1);
                *reinterpret_cast<float2*>(&outp[(size_t)(grow + 8) * Sc + gcol]) = make_float2(e2, e3);
                accS[nt][0] = e0; accS[nt][1] = e1; accS[nt][2] = e2; accS[nt][3] = e3;
            }

            // ---- PV over this k-strip half: shuffle-transpose accS -> A frags
#pragma unroll
            for (int s4 = 0; s4 < 4; s4++) {
                float x0 = __shfl_sync(0xffffffffu, accS[s4][0], src1);
                float x1 = __shfl_sync(0xffffffffu, accS[s4][1], src1);
                float y0 = __shfl_sync(0xffffffffu, accS[s4][2], src1);
                float y1 = __shfl_sync(0xffffffffu, accS[s4][3], src1);
                float z0 = __shfl_sync(0xffffffffu, accS[s4][0], src2);
                float z1 = __shfl_sync(0xffffffffu, accS[s4][1], src2);
                float w0 = __shfl_sync(0xffffffffu, accS[s4][2], src2);
                float w1 = __shfl_sync(0xffffffffu, accS[s4][3], src2);
                uint32_t af[4];
                af[0] = f2tf(odd ? x1 : x0);
                af[1] = f2tf(odd ? y1 : y0);
                af[2] = f2tf(odd ? z1 : z0);
                af[3] = f2tf(odd ? w1 : w0);
                const int vr = colbase + s4 * 8 + c;   // V row (k) within tile
#pragma unroll
                for (int nt = 0; nt < 8; nt++) {
                    uint32_t bf[2];
                    bf[0] = __float_as_uint(sV[vr * 68 + nt * 8 + g]);
                    bf[1] = __float_as_uint(sV[(vr + 4) * 68 + nt * 8 + g]);
                    mma8(accU[nt], af, bf);
                }
            }
        }

        if (kt + 1 < 16) cpa_wait0();
        __syncthreads();
    }

    // ---- rowsum reduction -> inv ----
    float* red  = smf + FRED;
    float* red2 = smf + FRED2;
    {
        float v0 = rs0, v1 = rs1;
        v0 += __shfl_xor_sync(0xffffffffu, v0, 1);
        v0 += __shfl_xor_sync(0xffffffffu, v0, 2);
        v1 += __shfl_xor_sync(0xffffffffu, v1, 1);
        v1 += __shfl_xor_sync(0xffffffffu, v1, 2);
        if (c == 0) {
            red[(wm * 16 + g) * 2 + wn]     = v0;
            red[(wm * 16 + g + 8) * 2 + wn] = v1;
        }
    }
    __syncthreads();
    if (tid < 128) {
        float ssum = red[tid * 2] + red[tid * 2 + 1];
        float iv = 1.0f / ssum;
        invg[(size_t)bh * Sc + row0 + tid] = iv;
        red2[tid] = iv;
    }
    __syncthreads();

    // ---- cross-warp U reduction (wn=1 -> smem, wn=0 adds + writes ctx) ----
    float* uRed = smf;   // reuse K0 region, stride 68
    if (wn == 1) {
#pragma unroll
        for (int nt = 0; nt < 8; nt++) {
            int rr = wm * 16 + g, cc = nt * 8 + c * 2;
            uRed[rr * 68 + cc]           = accU[nt][0];
            uRed[rr * 68 + cc + 1]       = accU[nt][1];
            uRed[(rr + 8) * 68 + cc]     = accU[nt][2];
            uRed[(rr + 8) * 68 + cc + 1] = accU[nt][3];
        }
    }
    __syncthreads();
    if (wn == 0) {
        float* cp = ctx + (size_t)(b * Sc + row0) * Dc + h * HDc;
        int rr = wm * 16 + g;
        float iv0 = red2[rr], iv1 = red2[rr + 8];
#pragma unroll
        for (int nt = 0; nt < 8; nt++) {
            int cc = nt * 8 + c * 2;
            float u0 = accU[nt][0] + uRed[rr * 68 + cc];
            float u1 = accU[nt][1] + uRed[rr * 68 + cc + 1];
            float u2 = accU[nt][2] + uRed[(rr + 8) * 68 + cc];
            float u3 = accU[nt][3] + uRed[(rr + 8) * 68 + cc + 1];
            cp[(size_t)rr * Dc + cc]           = u0 * iv0;
            cp[(size_t)rr * Dc + cc + 1]       = u1 * iv0;
            cp[(size_t)(rr + 8) * Dc + cc]     = u2 * iv1;
            cp[(size_t)(rr + 8) * Dc + cc + 1] = u3 * iv1;
        }
    }
}

// ============================================================================
// normalize attn in place: attn[row, :] *= inv[row]   (pure bandwidth)
// ============================================================================
__global__ void norm_k(float4* __restrict__ attn4, const float* __restrict__ inv) {
    const size_t total = (size_t)BHc * Sc * Sc / 4;
    size_t i = (size_t)blockIdx.x * blockDim.x + threadIdx.x;
    const size_t stride = (size_t)gridDim.x * blockDim.x;
    for (; i < total; i += stride) {
        float s = __ldg(&inv[i >> 9]);     // 512 float4 per row
        float4 v = attn4[i];
        v.x *= s; v.y *= s; v.z *= s; v.w *= s;
        attn4[i] = v;
    }
}

// ---------------------------------------------------------------------------
extern "C" void kernel_launch(void* const* d_in, const int* in_sizes, int n_in,
                              void* d_out, int out_size) {
    const float* query = (const float*)d_in[0];
    const float* key   = (const float*)d_in[1];
    const float* value = (const float*)d_in[2];
    const float* Wq = (const float*)d_in[3];
    const float* bq = (const float*)d_in[4];
    const float* Wk = (const float*)d_in[5];
    const float* bk = (const float*)d_in[6];
    const float* Wv = (const float*)d_in[7];
    const float* bv = (const float*)d_in[8];
    const float* Wo = (const float*)d_in[9];
    const float* bo = (const float*)d_in[10];

    float* out = (float*)d_out;
    const size_t OUT_E  = (size_t)Bc * Sc * Dc;
    const size_t ATTN_E = (size_t)BHc * Sc * Sc;

    float* attn;
    if ((size_t)out_size >= OUT_E + ATTN_E) {
        attn = out + OUT_E;
    } else {
        void* p = nullptr; cudaGetSymbolAddress(&p, g_attn_fb); attn = (float*)p;
    }
    float* Qp;   { void* p; cudaGetSymbolAddress(&p, g_Q);      Qp = (float*)p; }
    float* Kp;   { void* p; cudaGetSymbolAddress(&p, g_K);      Kp = (float*)p; }
    float* Vp;   { void* p; cudaGetSymbolAddress(&p, g_V);      Vp = (float*)p; }
    float* Cx;   { void* p; cudaGetSymbolAddress(&p, g_ctx);    Cx = (float*)p; }
    float* isum; { void* p; cudaGetSymbolAddress(&p, g_invsum); isum = (float*)p; }

    cudaFuncSetAttribute(fused_attn, cudaFuncAttributeMaxDynamicSharedMemorySize,
                         FTOT * 4);

    const int M = Bc * Sc;                      // 4096
    dim3 thr(256);
    dim3 gproj(Dc / 128, M / 128);              // (8, 32)

    gemm_bias_tc<<<gproj, thr>>>(query, Wq, bq, Qp, M, Dc, Dc);
    gemm_bias_tc<<<gproj, thr>>>(key,   Wk, bk, Kp, M, Dc, Dc);
    gemm_bias_tc<<<gproj, thr>>>(value, Wv, bv, Vp, M, Dc, Dc);

    dim3 gfa(Sc / 128, BHc);                    // (16, 32)
    fused_attn<<<gfa, dim3(512), FTOT * 4>>>(Qp, Kp, Vp, attn, isum, Cx);

    norm_k<<<4736, 256>>>((float4*)attn, isum);

    gemm_bias_tc<<<gproj, thr>>>(Cx, Wo, bo, out, M, Dc, Dc);
}